// round 14
// baseline (speedup 1.0000x reference)
#include <cuda_runtime.h>
#include <cuda_bf16.h>
#include <cuda_fp16.h>
#include <math.h>
#include <stdint.h>

// Problem constants
#define BB     2
#define CC     512
#define HEADS  8
#define DPH    16
#define TOT    128          // HEADS*DPH
#define NN     2304         // 48*48
#define M_QKV  384          // 3*TOT
#define K_QKV  512
#define M_PRJ  512
#define K_PRJ  128
#define NSPLIT 3
#define CHUNK  (NN / NSPLIT)   // 768
#define QBLKS  (NN / 128)      // 18
#define NSLOT  72              // proj BN slots: 36 n-blocks x 2 batches

// Scratch (device globals — no allocation allowed)
__device__ float g_q [BB*HEADS*NN*DPH];   // [b][h][n][d]  (UNNORMALIZED)
__device__ float g_k [BB*HEADS*NN*DPH];
__device__ float g_v [BB*HEADS*NN*DPH];
__device__ float g_ao[BB*TOT*NN];         // [b][t][n]
__device__ float g_part[NSPLIT*BB*HEADS*DPH*NN];
__device__ float g_lsum[NSPLIT*BB*HEADS*NN];
__device__ float g_bnpart2[NSLOT*CC*2];   // [slot][c][{s,s2}]
__device__ float g_bnscale[CC];
__device__ float g_bnshift[CC];

__device__ __forceinline__ uint32_t f2tf32(float f) {
    uint32_t u;
    asm("cvt.rna.tf32.f32 %0, %1;" : "=r"(u) : "f"(f));
    return u;
}
__device__ __forceinline__ float tf32_round(float f) {
    return __uint_as_float(f2tf32(f));
}
__device__ __forceinline__ float ex2f(float x) {
    float r;
    asm("ex2.approx.ftz.f32 %0, %1;" : "=f"(r) : "f"(x));
    return r;
}
__device__ __forceinline__ void mma_tf32(float* c,
                                         const uint32_t* a,
                                         uint32_t b0, uint32_t b1) {
    asm volatile("mma.sync.aligned.m16n8k8.row.col.f32.tf32.tf32.f32 "
                 "{%0,%1,%2,%3}, {%4,%5,%6,%7}, {%8,%9}, {%0,%1,%2,%3};"
                 : "+f"(c[0]), "+f"(c[1]), "+f"(c[2]), "+f"(c[3])
                 : "r"(a[0]), "r"(a[1]), "r"(a[2]), "r"(a[3]), "r"(b0), "r"(b1));
}
__device__ __forceinline__ void mma_bf16(float* c,
                                         const uint32_t* a,
                                         uint32_t b0, uint32_t b1) {
    asm volatile("mma.sync.aligned.m16n8k16.row.col.f32.bf16.bf16.f32 "
                 "{%0,%1,%2,%3}, {%4,%5,%6,%7}, {%8,%9}, {%0,%1,%2,%3};"
                 : "+f"(c[0]), "+f"(c[1]), "+f"(c[2]), "+f"(c[3])
                 : "r"(a[0]), "r"(a[1]), "r"(a[2]), "r"(a[3]), "r"(b0), "r"(b1));
}
__device__ __forceinline__ void mma_f16(float* c,
                                        const uint32_t* a,
                                        uint32_t b0, uint32_t b1) {
    asm volatile("mma.sync.aligned.m16n8k16.row.col.f32.f16.f16.f32 "
                 "{%0,%1,%2,%3}, {%4,%5,%6,%7}, {%8,%9}, {%0,%1,%2,%3};"
                 : "+f"(c[0]), "+f"(c[1]), "+f"(c[2]), "+f"(c[3])
                 : "r"(a[0]), "r"(a[1]), "r"(a[2]), "r"(a[3]), "r"(b0), "r"(b1));
}
__device__ __forceinline__ uint32_t pack2bf(float lo_elem, float hi_elem) {
    uint32_t r;
    asm("cvt.rn.bf16x2.f32 %0, %1, %2;" : "=r"(r) : "f"(hi_elem), "f"(lo_elem));
    return r;
}
__device__ __forceinline__ uint32_t pack2h(float lo_elem, float hi_elem) {
    uint32_t r;
    asm("cvt.rn.f16x2.f32 %0, %1, %2;" : "=r"(r) : "f"(hi_elem), "f"(lo_elem));
    return r;
}
__device__ __forceinline__ uint32_t split_lo2(uint32_t hpk, float e0, float e1) {
    float h0 = __uint_as_float(hpk << 16);
    float h1 = __uint_as_float(hpk & 0xFFFF0000u);
    return pack2bf(e0 - h0, e1 - h1);
}
__device__ __forceinline__ void ldsm_x2_trans(uint32_t& r0, uint32_t& r1, uint32_t saddr) {
    asm volatile("ldmatrix.sync.aligned.m8n8.x2.trans.shared.b16 {%0,%1}, [%2];"
                 : "=r"(r0), "=r"(r1) : "r"(saddr));
}
__device__ __forceinline__ void ldsm_x4(uint32_t* r, uint32_t saddr) {
    asm volatile("ldmatrix.sync.aligned.m8n8.x4.shared.b16 {%0,%1,%2,%3}, [%4];"
                 : "=r"(r[0]), "=r"(r[1]), "=r"(r[2]), "=r"(r[3]) : "r"(saddr));
}

// ===========================================================================
// Split-bf16 GEMM, double-buffered. "finish" functor handles the epilogue
// and may reuse the 38 KB smem region passed as scratch (post final sync).
// ===========================================================================
#define AWS 20
#define BSTRB 72
#define SM_AH   0
#define SM_AL   10240
#define SM_BH   20480
#define SM_BL   29696
#define SM_TOT  38912

template <int KDIM, typename Fin>
__device__ __forceinline__ void gemm_body(const float* __restrict__ A,
                                          const float* __restrict__ B,
                                          Fin finish) {
    __shared__ __align__(16) unsigned char smraw[SM_TOT];
    uint32_t*      Ah0 = (uint32_t*)(smraw + SM_AH);       // [2][1280]
    uint32_t*      Al0 = (uint32_t*)(smraw + SM_AL);
    __nv_bfloat16* Bh0 = (__nv_bfloat16*)(smraw + SM_BH);  // [2][2304]
    __nv_bfloat16* Bl0 = (__nv_bfloat16*)(smraw + SM_BL);
    const int tid  = threadIdx.x;
    const int lane = tid & 31;
    const int wid  = tid >> 5;
    const int gr   = lane >> 2;
    const int ct   = lane & 3;
    const int wm   = (wid & 1) * 32;
    const int wn   = (wid >> 1) * 16;
    const int mBase = blockIdx.y * 64;
    const int nBase = blockIdx.x * 64;
    const int lrow = lane & 15;
    const int arow_off  = ((lane >> 3) & 1) * 8 + (lane & 7);
    const int acolw_off = (lane >> 4) * 4;

    int am[2], ak[2], bk[2], bn[2];
    #pragma unroll
    for (int t = 0; t < 2; t++) {
        int i4 = tid + t * 256;
        am[t] = i4 >> 3;  ak[t] = (i4 & 7) << 2;
        bk[t] = i4 >> 4;  bn[t] = (i4 & 15) << 2;
    }
    float4 areg[2], breg[2];
    #pragma unroll
    for (int t = 0; t < 2; t++) {
        areg[t] = *(const float4*)&A[(mBase + am[t]) * KDIM + ak[t]];
        breg[t] = *(const float4*)&B[(size_t)bk[t] * NN + nBase + bn[t]];
    }
    #pragma unroll
    for (int t = 0; t < 2; t++) {
        uint32_t ah0 = pack2bf(areg[t].x, areg[t].y);
        uint32_t ah1 = pack2bf(areg[t].z, areg[t].w);
        uint32_t al0 = split_lo2(ah0, areg[t].x, areg[t].y);
        uint32_t al1 = split_lo2(ah1, areg[t].z, areg[t].w);
        int awi = am[t]*AWS + (ak[t] >> 1);
        *(uint2*)&Ah0[awi] = make_uint2(ah0, ah1);
        *(uint2*)&Al0[awi] = make_uint2(al0, al1);
        uint32_t bh0 = pack2bf(breg[t].x, breg[t].y);
        uint32_t bh1 = pack2bf(breg[t].z, breg[t].w);
        uint32_t bl0 = split_lo2(bh0, breg[t].x, breg[t].y);
        uint32_t bl1 = split_lo2(bh1, breg[t].z, breg[t].w);
        int bwi = (bk[t]*BSTRB + bn[t]) >> 1;
        *(uint2*)&((uint32_t*)Bh0)[bwi] = make_uint2(bh0, bh1);
        *(uint2*)&((uint32_t*)Bl0)[bwi] = make_uint2(bl0, bl1);
    }
    __syncthreads();

    float c[2][2][4] = {};
    #pragma unroll 2
    for (int ch = 0; ch < KDIM/32; ch++) {
        const int cur = ch & 1;
        const bool more = (ch + 1 < KDIM/32);
        uint32_t*      AhC = Ah0 + cur*1280;
        uint32_t*      AlC = Al0 + cur*1280;
        __nv_bfloat16* BhC = Bh0 + cur*2304;
        __nv_bfloat16* BlC = Bl0 + cur*2304;
        if (more) {
            #pragma unroll
            for (int t = 0; t < 2; t++) {
                areg[t] = *(const float4*)&A[(mBase + am[t]) * KDIM + (ch+1)*32 + ak[t]];
                breg[t] = *(const float4*)&B[(size_t)((ch+1)*32 + bk[t]) * NN + nBase + bn[t]];
            }
        }
        #pragma unroll
        for (int s = 0; s < 2; s++) {
            const int kwo = s * 8;
            const int kro = s * 16;
            uint32_t ah[2][4], al2[2][4];
            #pragma unroll
            for (int mt = 0; mt < 2; mt++) {
                int m0 = wm + mt*16;
                int aidx = (m0 + arow_off)*AWS + kwo + acolw_off;
                uint32_t hadr = (uint32_t)__cvta_generic_to_shared(&AhC[aidx]);
                uint32_t ladr = (uint32_t)__cvta_generic_to_shared(&AlC[aidx]);
                ldsm_x4(ah[mt],  hadr);
                ldsm_x4(al2[mt], ladr);
            }
            uint32_t bhf[2][2], blf[2][2];
            #pragma unroll
            for (int nt = 0; nt < 2; nt++) {
                int n0 = wn + nt*8;
                uint32_t hadr = (uint32_t)__cvta_generic_to_shared(
                    &BhC[(kro + lrow)*BSTRB + n0]);
                uint32_t ladr = (uint32_t)__cvta_generic_to_shared(
                    &BlC[(kro + lrow)*BSTRB + n0]);
                ldsm_x2_trans(bhf[nt][0], bhf[nt][1], hadr);
                ldsm_x2_trans(blf[nt][0], blf[nt][1], ladr);
            }
            #pragma unroll
            for (int mt = 0; mt < 2; mt++)
            #pragma unroll
            for (int nt = 0; nt < 2; nt++) {
                mma_bf16(c[mt][nt], ah[mt],  bhf[nt][0], bhf[nt][1]);
                mma_bf16(c[mt][nt], ah[mt],  blf[nt][0], blf[nt][1]);
                mma_bf16(c[mt][nt], al2[mt], bhf[nt][0], bhf[nt][1]);
            }
        }
        if (more) {
            const int nxt = cur ^ 1;
            uint32_t*      AhN = Ah0 + nxt*1280;
            uint32_t*      AlN = Al0 + nxt*1280;
            uint32_t*      BhN = (uint32_t*)(Bh0 + nxt*2304);
            uint32_t*      BlN = (uint32_t*)(Bl0 + nxt*2304);
            #pragma unroll
            for (int t = 0; t < 2; t++) {
                uint32_t ah0 = pack2bf(areg[t].x, areg[t].y);
                uint32_t ah1 = pack2bf(areg[t].z, areg[t].w);
                uint32_t al0 = split_lo2(ah0, areg[t].x, areg[t].y);
                uint32_t al1 = split_lo2(ah1, areg[t].z, areg[t].w);
                int awi = am[t]*AWS + (ak[t] >> 1);
                *(uint2*)&AhN[awi] = make_uint2(ah0, ah1);
                *(uint2*)&AlN[awi] = make_uint2(al0, al1);
                uint32_t bh0 = pack2bf(breg[t].x, breg[t].y);
                uint32_t bh1 = pack2bf(breg[t].z, breg[t].w);
                uint32_t bl0 = split_lo2(bh0, breg[t].x, breg[t].y);
                uint32_t bl1 = split_lo2(bh1, breg[t].z, breg[t].w);
                int bwi = (bk[t]*BSTRB + bn[t]) >> 1;
                *(uint2*)&BhN[bwi] = make_uint2(bh0, bh1);
                *(uint2*)&BlN[bwi] = make_uint2(bl0, bl1);
            }
        }
        __syncthreads();
    }
    finish(c, (float*)smraw);
}

// K1: qkv = w_qkv[384,512] @ x[b,512,2304]; scatter into q/k/v [b,h,n,d].
// Epilogue: transpose via smem (layout n*68+h*16+d, conflict-free STS),
// then fully-coalesced float4 stores.
__global__ void __launch_bounds__(256) qkv_mma(const float* __restrict__ x,
                                               const float* __restrict__ w) {
    const int b = blockIdx.z;
    const float* xb = x + (size_t)b * CC * NN;
    gemm_body<K_QKV>(w, xb, [b](const float (&c)[2][2][4], float* scratch) {
        const int tid  = threadIdx.x;
        const int lane = tid & 31;
        const int wid  = tid >> 5;
        const int gr   = lane >> 2;
        const int ct   = lane & 3;
        const int wm   = (wid & 1) * 32;
        const int wn   = (wid >> 1) * 16;
        const int mBase = blockIdx.y * 64;
        const int nBase = blockIdx.x * 64;
        #pragma unroll
        for (int mt = 0; mt < 2; mt++)
        #pragma unroll
        for (int nt = 0; nt < 2; nt++)
        #pragma unroll
        for (int e = 0; e < 4; e++) {
            int rloc = wm + mt*16 + gr + ((e >= 2) ? 8 : 0);
            int nloc = wn + nt*8 + 2*ct + (e & 1);
            scratch[nloc*68 + (rloc >> 4)*16 + (rloc & 15)] = c[mt][nt][e];
        }
        __syncthreads();
        const int part = mBase >> 7;
        float* dst = (part == 0) ? g_q : ((part == 1) ? g_k : g_v);
        const int hbase = (mBase & 127) >> 4;
        #pragma unroll
        for (int t = 0; t < 4; t++) {
            int j    = tid + t*256;          // 1024 float4 tasks
            int hp   = j >> 8;               // head-in-block 0..3
            int rem  = j & 255;
            int nloc = rem >> 2;
            int dc   = rem & 3;
            float4 v = *(float4*)&scratch[nloc*68 + hp*16 + dc*4];
            ((float4*)dst)[(((size_t)(b*HEADS + hbase + hp))*NN + nBase + nloc)*4 + dc] = v;
        }
    });
}

// K4: out[b,c,n] = w_out[512,128] @ ao[b,128,2304].
// Epilogue: float2-paired stores + deterministic per-block BN partials.
__global__ void __launch_bounds__(256) proj_mma(const float* __restrict__ w,
                                                float* __restrict__ out) {
    const int b = blockIdx.z;
    const float* ao = g_ao + (size_t)b * TOT * NN;
    gemm_body<K_PRJ>(w, ao, [b, out](const float (&c)[2][2][4], float* scratch) {
        const int tid  = threadIdx.x;
        const int lane = tid & 31;
        const int wid  = tid >> 5;
        const int gr   = lane >> 2;
        const int ct   = lane & 3;
        const int wm   = (wid & 1) * 32;
        const int wn   = (wid >> 1) * 16;
        const int mBase = blockIdx.y * 64;
        const int nBase = blockIdx.x * 64;
        // paired stores
        #pragma unroll
        for (int mt = 0; mt < 2; mt++)
        #pragma unroll
        for (int nt = 0; nt < 2; nt++) {
            int m0 = mBase + wm + mt*16 + gr;
            int n0 = nBase + wn + nt*8 + 2*ct;
            *(float2*)&out[((size_t)b*CC + m0    )*NN + n0] = make_float2(c[mt][nt][0], c[mt][nt][1]);
            *(float2*)&out[((size_t)b*CC + m0 + 8)*NN + n0] = make_float2(c[mt][nt][2], c[mt][nt][3]);
        }
        // BN partials: per-row sums over this block's 64 n-columns
        #pragma unroll
        for (int mt = 0; mt < 2; mt++)
        #pragma unroll
        for (int half = 0; half < 2; half++) {
            float s = 0.f, s2 = 0.f;
            #pragma unroll
            for (int nt = 0; nt < 2; nt++) {
                float v0 = c[mt][nt][half*2 + 0];
                float v1 = c[mt][nt][half*2 + 1];
                s  += v0 + v1;
                s2 += v0*v0 + v1*v1;
            }
            s  += __shfl_xor_sync(0xffffffffu, s, 1);
            s  += __shfl_xor_sync(0xffffffffu, s, 2);
            s2 += __shfl_xor_sync(0xffffffffu, s2, 1);
            s2 += __shfl_xor_sync(0xffffffffu, s2, 2);
            if (ct == 0) {
                int rloc = wm + mt*16 + gr + half*8;
                scratch[(rloc*4 + (wid >> 1))*2 + 0] = s;
                scratch[(rloc*4 + (wid >> 1))*2 + 1] = s2;
            }
        }
        __syncthreads();
        if (tid < 128) {
            int rloc = tid >> 1, q = tid & 1;
            float v = scratch[(rloc*4+0)*2 + q] + scratch[(rloc*4+1)*2 + q]
                    + scratch[(rloc*4+2)*2 + q] + scratch[(rloc*4+3)*2 + q];
            int slot = blockIdx.x*2 + b;
            g_bnpart2[((size_t)slot*CC + (mBase + rloc))*2 + q] = v;
        }
    });
}

// ===========================================================================
// K3: attention (unchanged, proven): 3-way key split, tf32 S, f16 PV.
// ===========================================================================
#define KSTR 20
#define VWS  68
__global__ void __launch_bounds__(256) attn_mma(const float* __restrict__ temperature) {
    __shared__ float Ks[128*KSTR];
    __shared__ __align__(4) uint32_t Vw[16*VWS];
    const int b     = blockIdx.z;
    const int h     = blockIdx.y;
    const int split = blockIdx.x / QBLKS;
    const int qblk  = blockIdx.x % QBLKS;
    const int tid  = threadIdx.x;
    const int wid  = tid >> 5;
    const int lane = tid & 31;
    const int gr   = lane >> 2;
    const int ct   = lane & 3;
    const float scale = __ldg(&temperature[h]) * 1.4426950408889634f;
    const int base = (b*HEADS + h) * NN * DPH;
    const int qw   = qblk * 128 + wid * 16;
    const int cstart = split * CHUNK;

    uint32_t qa[2][4];
    {
        const float* q0 = g_q + base + (qw+gr  )*DPH;
        const float* q1 = g_q + base + (qw+gr+8)*DPH;
        float r0[4], r1[4];
        #pragma unroll
        for (int j = 0; j < 4; j++) { r0[j] = q0[ct + 4*j]; r1[j] = q1[ct + 4*j]; }
        float s0 = r0[0]*r0[0] + r0[1]*r0[1] + r0[2]*r0[2] + r0[3]*r0[3];
        float s1 = r1[0]*r1[0] + r1[1]*r1[1] + r1[2]*r1[2] + r1[3]*r1[3];
        s0 += __shfl_xor_sync(0xffffffffu, s0, 1);
        s0 += __shfl_xor_sync(0xffffffffu, s0, 2);
        s1 += __shfl_xor_sync(0xffffffffu, s1, 1);
        s1 += __shfl_xor_sync(0xffffffffu, s1, 2);
        float i0 = scale / fmaxf(sqrtf(s0), 1e-12f);
        float i1 = scale / fmaxf(sqrtf(s1), 1e-12f);
        qa[0][0] = f2tf32(r0[0]*i0); qa[0][1] = f2tf32(r1[0]*i1);
        qa[0][2] = f2tf32(r0[1]*i0); qa[0][3] = f2tf32(r1[1]*i1);
        qa[1][0] = f2tf32(r0[2]*i0); qa[1][1] = f2tf32(r1[2]*i1);
        qa[1][2] = f2tf32(r0[3]*i0); qa[1][3] = f2tf32(r1[3]*i1);
    }

    float out0[4] = {};
    float out1[4] = {};
    float l0 = 0.f, l1 = 0.f;
    const uint32_t* ksu = (const uint32_t*)Ks;
    const int koff = gr * KSTR + ct;

    for (int t0 = 0; t0 < CHUNK; t0 += 128) {
        __syncthreads();
        {
            const float4* kg = (const float4*)(g_k + base + (cstart + t0)*16);
            const float4* vg = (const float4*)(g_v + base + (cstart + t0)*16);
            __half* vb = (__half*)Vw;
            #pragma unroll
            for (int t = 0; t < 2; t++) {
                int i4 = tid + t * 256;
                int r = i4 >> 2, cc4 = (i4 & 3) * 4;
                float4 kv = kg[i4];
                float s = kv.x*kv.x + kv.y*kv.y + kv.z*kv.z + kv.w*kv.w;
                s += __shfl_xor_sync(0xffffffffu, s, 1);
                s += __shfl_xor_sync(0xffffffffu, s, 2);
                float inv = 1.0f / fmaxf(sqrtf(s), 1e-12f);
                kv.x = tf32_round(kv.x * inv); kv.y = tf32_round(kv.y * inv);
                kv.z = tf32_round(kv.z * inv); kv.w = tf32_round(kv.w * inv);
                *(float4*)&Ks[r*KSTR + cc4] = kv;
                float4 vv = vg[i4];
                int half_i = r & 1, k2 = r >> 1;
                vb[((cc4+0)*VWS + k2)*2 + half_i] = __float2half_rn(vv.x);
                vb[((cc4+1)*VWS + k2)*2 + half_i] = __float2half_rn(vv.y);
                vb[((cc4+2)*VWS + k2)*2 + half_i] = __float2half_rn(vv.z);
                vb[((cc4+3)*VWS + k2)*2 + half_i] = __float2half_rn(vv.w);
            }
        }
        __syncthreads();
        #pragma unroll 4
        for (int kb16 = 0; kb16 < 8; kb16++) {
            float sa[4] = {};
            {
                int ka = (kb16*16)*KSTR + koff;
                mma_tf32(sa, qa[0], ksu[ka],   ksu[ka+4]);
                mma_tf32(sa, qa[1], ksu[ka+8], ksu[ka+12]);
            }
            float sb[4] = {};
            {
                int ka = (kb16*16 + 8)*KSTR + koff;
                mma_tf32(sb, qa[0], ksu[ka],   ksu[ka+4]);
                mma_tf32(sb, qa[1], ksu[ka+8], ksu[ka+12]);
            }
            float pa0 = ex2f(sa[0]), pa1 = ex2f(sa[1]);
            float pa2 = ex2f(sa[2]), pa3 = ex2f(sa[3]);
            float pb0 = ex2f(sb[0]), pb1 = ex2f(sb[1]);
            float pb2 = ex2f(sb[2]), pb3 = ex2f(sb[3]);
            l0 += (pa0 + pa1) + (pb0 + pb1);
            l1 += (pa2 + pa3) + (pb2 + pb3);
            uint32_t pH[4];
            pH[0] = pack2h(pa0, pa1);
            pH[1] = pack2h(pa2, pa3);
            pH[2] = pack2h(pb0, pb1);
            pH[3] = pack2h(pb2, pb3);
            {
                int kbase = kb16*8 + ct;
                mma_f16(out0, pH, Vw[gr*VWS + kbase],     Vw[gr*VWS + kbase + 4]);
                mma_f16(out1, pH, Vw[(8+gr)*VWS + kbase], Vw[(8+gr)*VWS + kbase + 4]);
            }
        }
    }
    l0 += __shfl_xor_sync(0xffffffffu, l0, 1);
    l0 += __shfl_xor_sync(0xffffffffu, l0, 2);
    l1 += __shfl_xor_sync(0xffffffffu, l1, 1);
    l1 += __shfl_xor_sync(0xffffffffu, l1, 2);

    const int bh = b*HEADS + h;
    float* pp = g_part + ((size_t)(split*BB*HEADS + bh) * DPH) * NN;
    {
        int d0 = 2*ct;
        pp[(size_t)(d0    )*NN + qw + gr    ] = out0[0];
        pp[(size_t)(d0 + 1)*NN + qw + gr    ] = out0[1];
        pp[(size_t)(d0    )*NN + qw + gr + 8] = out0[2];
        pp[(size_t)(d0 + 1)*NN + qw + gr + 8] = out0[3];
        pp[(size_t)(8 + d0    )*NN + qw + gr    ] = out1[0];
        pp[(size_t)(8 + d0 + 1)*NN + qw + gr    ] = out1[1];
        pp[(size_t)(8 + d0    )*NN + qw + gr + 8] = out1[2];
        pp[(size_t)(8 + d0 + 1)*NN + qw + gr + 8] = out1[3];
        float* lp = g_lsum + (size_t)(split*BB*HEADS + bh) * NN;
        lp[qw + gr    ] = l0;
        lp[qw + gr + 8] = l1;
    }
}

// K3b: combine split partials, normalize, write g_ao. Coalesced.
__global__ void __launch_bounds__(256) combine_kernel() {
    int idx = blockIdx.x * 256 + threadIdx.x;
    const int NQ4 = NN / 4;
    int n4 = idx % NQ4;
    int r  = idx / NQ4;
    int d  = r & 15;
    int bh = r >> 4;
    float4 acc = make_float4(0.f, 0.f, 0.f, 0.f);
    float4 lac = make_float4(0.f, 0.f, 0.f, 0.f);
    #pragma unroll
    for (int s = 0; s < NSPLIT; s++) {
        float4 p = *(const float4*)&g_part[((size_t)(s*BB*HEADS + bh) * DPH + d) * NN + n4*4];
        float4 l = *(const float4*)&g_lsum[(size_t)(s*BB*HEADS + bh) * NN + n4*4];
        acc.x += p.x; acc.y += p.y; acc.z += p.z; acc.w += p.w;
        lac.x += l.x; lac.y += l.y; lac.z += l.z; lac.w += l.w;
    }
    float4 o;
    o.x = acc.x / lac.x; o.y = acc.y / lac.y;
    o.z = acc.z / lac.z; o.w = acc.w / lac.w;
    *(float4*)&g_ao[(size_t)(bh*DPH + d) * NN + n4*4] = o;
}

// K5b: finalize scale/shift per channel from NSLOT proj-block partials.
__global__ void __launch_bounds__(256) bn_finalize(const float* __restrict__ gamma,
                                                   const float* __restrict__ beta) {
    int c = blockIdx.x * 256 + threadIdx.x;
    if (c >= CC) return;
    float s = 0.f, s2 = 0.f;
    #pragma unroll 8
    for (int sl = 0; sl < NSLOT; sl++) {
        s  += g_bnpart2[((size_t)sl*CC + c)*2 + 0];
        s2 += g_bnpart2[((size_t)sl*CC + c)*2 + 1];
    }
    const float invN = 1.0f / (BB * NN);
    float mean = s * invN;
    float var  = fmaxf(s2 * invN - mean * mean, 0.f);
    float sc   = rsqrtf(var + 1e-5f) * gamma[c];
    g_bnscale[c] = sc;
    g_bnshift[c] = beta[c] - mean * sc;
}

// K5c: apply. grid = BB*CC*NN/4/256 = 2304 blocks.
__global__ void __launch_bounds__(256) bn_apply(float* __restrict__ out) {
    int fi = blockIdx.x * 256 + threadIdx.x;
    int c  = ((fi * 4) / NN) % CC;
    float sc = g_bnscale[c], sh = g_bnshift[c];
    float4* p = (float4*)out + fi;
    float4 v = *p;
    v.x = fmaf(v.x, sc, sh); v.y = fmaf(v.y, sc, sh);
    v.z = fmaf(v.z, sc, sh); v.w = fmaf(v.w, sc, sh);
    *p = v;
}

// ---------------------------------------------------------------------------
extern "C" void kernel_launch(void* const* d_in, const int* in_sizes, int n_in,
                              void* d_out, int out_size) {
    const float* x      = (const float*)d_in[0];
    const float* w_qkv  = (const float*)d_in[1];
    const float* temper = (const float*)d_in[2];
    const float* w_out  = (const float*)d_in[3];
    const float* gamma  = (const float*)d_in[4];
    const float* beta   = (const float*)d_in[5];
    float* out = (float*)d_out;

    qkv_mma <<<dim3(NN/64, M_QKV/64, BB), 256>>>(x, w_qkv);
    attn_mma<<<dim3(QBLKS*NSPLIT, HEADS, BB), 256>>>(temper);
    combine_kernel<<<(BB*HEADS*DPH*NN/4)/256, 256>>>();
    proj_mma<<<dim3(NN/64, M_PRJ/64, BB), 256>>>(w_out, out);
    bn_finalize<<<2, 256>>>(gamma, beta);
    bn_apply<<<(BB*CC*NN/4)/256, 256>>>(out);
}

// round 15
// speedup vs baseline: 1.1016x; 1.1016x over previous
#include <cuda_runtime.h>
#include <cuda_bf16.h>
#include <cuda_fp16.h>
#include <math.h>
#include <stdint.h>

// Problem constants
#define BB     2
#define CC     512
#define HEADS  8
#define DPH    16
#define TOT    128          // HEADS*DPH
#define NN     2304         // 48*48
#define M_QKV  384          // 3*TOT
#define K_QKV  512
#define M_PRJ  512
#define K_PRJ  128
#define NSPLIT 3
#define CHUNK  (NN / NSPLIT)   // 768
#define QBLKS  (NN / 128)      // 18
#define NSLOT  72              // proj BN slots: 36 n-blocks x 2 batches

// Scratch (device globals — no allocation allowed)
__device__ float g_q [BB*HEADS*NN*DPH];   // [b][h][n][d]  (UNNORMALIZED)
__device__ float g_k [BB*HEADS*NN*DPH];
__device__ float g_v [BB*HEADS*NN*DPH];
__device__ float g_ao[BB*TOT*NN];         // [b][t][n]
__device__ float g_part[NSPLIT*BB*HEADS*DPH*NN];
__device__ float g_lsum[NSPLIT*BB*HEADS*NN];
__device__ float g_bnpart2[NSLOT*CC*2];   // [slot][c][{s,s2}]
__device__ float g_bnscale[CC];
__device__ float g_bnshift[CC];

__device__ __forceinline__ uint32_t f2tf32(float f) {
    uint32_t u;
    asm("cvt.rna.tf32.f32 %0, %1;" : "=r"(u) : "f"(f));
    return u;
}
__device__ __forceinline__ float tf32_round(float f) {
    return __uint_as_float(f2tf32(f));
}
__device__ __forceinline__ float ex2f(float x) {
    float r;
    asm("ex2.approx.ftz.f32 %0, %1;" : "=f"(r) : "f"(x));
    return r;
}
__device__ __forceinline__ void mma_tf32(float* c,
                                         const uint32_t* a,
                                         uint32_t b0, uint32_t b1) {
    asm volatile("mma.sync.aligned.m16n8k8.row.col.f32.tf32.tf32.f32 "
                 "{%0,%1,%2,%3}, {%4,%5,%6,%7}, {%8,%9}, {%0,%1,%2,%3};"
                 : "+f"(c[0]), "+f"(c[1]), "+f"(c[2]), "+f"(c[3])
                 : "r"(a[0]), "r"(a[1]), "r"(a[2]), "r"(a[3]), "r"(b0), "r"(b1));
}
__device__ __forceinline__ void mma_f16(float* c,
                                        const uint32_t* a,
                                        uint32_t b0, uint32_t b1) {
    asm volatile("mma.sync.aligned.m16n8k16.row.col.f32.f16.f16.f32 "
                 "{%0,%1,%2,%3}, {%4,%5,%6,%7}, {%8,%9}, {%0,%1,%2,%3};"
                 : "+f"(c[0]), "+f"(c[1]), "+f"(c[2]), "+f"(c[3])
                 : "r"(a[0]), "r"(a[1]), "r"(a[2]), "r"(a[3]), "r"(b0), "r"(b1));
}
__device__ __forceinline__ uint32_t pack2h(float lo_elem, float hi_elem) {
    uint32_t r;
    asm("cvt.rn.f16x2.f32 %0, %1, %2;" : "=r"(r) : "f"(hi_elem), "f"(lo_elem));
    return r;
}
// residual (lo part) of a 2-term f16 split
__device__ __forceinline__ uint32_t split_lo2h(uint32_t hpk, float e0, float e1) {
    __half2 hv = *reinterpret_cast<__half2*>(&hpk);
    return pack2h(e0 - __low2float(hv), e1 - __high2float(hv));
}
__device__ __forceinline__ void ldsm_x2_trans(uint32_t& r0, uint32_t& r1, uint32_t saddr) {
    asm volatile("ldmatrix.sync.aligned.m8n8.x2.trans.shared.b16 {%0,%1}, [%2];"
                 : "=r"(r0), "=r"(r1) : "r"(saddr));
}
__device__ __forceinline__ void ldsm_x4(uint32_t* r, uint32_t saddr) {
    asm volatile("ldmatrix.sync.aligned.m8n8.x4.shared.b16 {%0,%1,%2,%3}, [%4];"
                 : "=r"(r[0]), "=r"(r[1]), "=r"(r[2]), "=r"(r[3]) : "r"(saddr));
}

// ===========================================================================
// 2-term-f16-split GEMM (C = A @ B):  C ≈ Ah*Bh + Ah*Bl.
// Dropped Al*B ~ 2^-11 rel (measured-calibrated total contribution ~3.3e-4).
// 8 MMAs per k16 step (was 12), A-lo staging/ldsm deleted. Double-buffered.
// "finish" functor gets accumulators + reusable smem scratch.
// ===========================================================================
#define AWS 20      // A row stride in 32-bit words (40 f16 = 80B: ldsm CF)
#define BSTRB 72    // B row stride in f16 elems
#define SM_AH   0                         // 2*1280 words = 10240 B
#define SM_BH   10240                     // 2*2304 f16  =  9216 B
#define SM_BL   19456                     //               9216 B
#define SM_TOT  28672

template <int KDIM, typename Fin>
__device__ __forceinline__ void gemm_body(const float* __restrict__ A,
                                          const float* __restrict__ B,
                                          Fin finish) {
    __shared__ __align__(16) unsigned char smraw[SM_TOT];
    uint32_t* Ah0 = (uint32_t*)(smraw + SM_AH);
    __half*   Bh0 = (__half*)(smraw + SM_BH);
    __half*   Bl0 = (__half*)(smraw + SM_BL);
    const int tid  = threadIdx.x;
    const int lane = tid & 31;
    const int wid  = tid >> 5;
    const int wm   = (wid & 1) * 32;
    const int wn   = (wid >> 1) * 16;
    const int mBase = blockIdx.y * 64;
    const int nBase = blockIdx.x * 64;
    const int lrow = lane & 15;
    const int arow_off  = ((lane >> 3) & 1) * 8 + (lane & 7);
    const int acolw_off = (lane >> 4) * 4;

    int am[2], ak[2], bk[2], bn[2];
    #pragma unroll
    for (int t = 0; t < 2; t++) {
        int i4 = tid + t * 256;
        am[t] = i4 >> 3;  ak[t] = (i4 & 7) << 2;
        bk[t] = i4 >> 4;  bn[t] = (i4 & 15) << 2;
    }
    float4 areg[2], breg[2];
    #pragma unroll
    for (int t = 0; t < 2; t++) {
        areg[t] = *(const float4*)&A[(mBase + am[t]) * KDIM + ak[t]];
        breg[t] = *(const float4*)&B[(size_t)bk[t] * NN + nBase + bn[t]];
    }
    #pragma unroll
    for (int t = 0; t < 2; t++) {
        uint32_t ah0 = pack2h(areg[t].x, areg[t].y);
        uint32_t ah1 = pack2h(areg[t].z, areg[t].w);
        int awi = am[t]*AWS + (ak[t] >> 1);
        *(uint2*)&Ah0[awi] = make_uint2(ah0, ah1);
        uint32_t bh0 = pack2h(breg[t].x, breg[t].y);
        uint32_t bh1 = pack2h(breg[t].z, breg[t].w);
        uint32_t bl0 = split_lo2h(bh0, breg[t].x, breg[t].y);
        uint32_t bl1 = split_lo2h(bh1, breg[t].z, breg[t].w);
        int bwi = (bk[t]*BSTRB + bn[t]) >> 1;
        *(uint2*)&((uint32_t*)Bh0)[bwi] = make_uint2(bh0, bh1);
        *(uint2*)&((uint32_t*)Bl0)[bwi] = make_uint2(bl0, bl1);
    }
    __syncthreads();

    float c[2][2][4] = {};
    #pragma unroll 2
    for (int ch = 0; ch < KDIM/32; ch++) {
        const int cur = ch & 1;
        const bool more = (ch + 1 < KDIM/32);
        uint32_t* AhC = Ah0 + cur*1280;
        __half*   BhC = Bh0 + cur*2304;
        __half*   BlC = Bl0 + cur*2304;
        if (more) {
            #pragma unroll
            for (int t = 0; t < 2; t++) {
                areg[t] = *(const float4*)&A[(mBase + am[t]) * KDIM + (ch+1)*32 + ak[t]];
                breg[t] = *(const float4*)&B[(size_t)((ch+1)*32 + bk[t]) * NN + nBase + bn[t]];
            }
        }
        #pragma unroll
        for (int s = 0; s < 2; s++) {
            const int kwo = s * 8;
            const int kro = s * 16;
            uint32_t ah[2][4];
            #pragma unroll
            for (int mt = 0; mt < 2; mt++) {
                int m0 = wm + mt*16;
                int aidx = (m0 + arow_off)*AWS + kwo + acolw_off;
                ldsm_x4(ah[mt], (uint32_t)__cvta_generic_to_shared(&AhC[aidx]));
            }
            uint32_t bhf[2][2], blf[2][2];
            #pragma unroll
            for (int nt = 0; nt < 2; nt++) {
                int n0 = wn + nt*8;
                ldsm_x2_trans(bhf[nt][0], bhf[nt][1],
                    (uint32_t)__cvta_generic_to_shared(&BhC[(kro + lrow)*BSTRB + n0]));
                ldsm_x2_trans(blf[nt][0], blf[nt][1],
                    (uint32_t)__cvta_generic_to_shared(&BlC[(kro + lrow)*BSTRB + n0]));
            }
            #pragma unroll
            for (int mt = 0; mt < 2; mt++)
            #pragma unroll
            for (int nt = 0; nt < 2; nt++) {
                mma_f16(c[mt][nt], ah[mt], bhf[nt][0], bhf[nt][1]);
                mma_f16(c[mt][nt], ah[mt], blf[nt][0], blf[nt][1]);
            }
        }
        if (more) {
            const int nxt = cur ^ 1;
            uint32_t* AhN = Ah0 + nxt*1280;
            uint32_t* BhN = (uint32_t*)(Bh0 + nxt*2304);
            uint32_t* BlN = (uint32_t*)(Bl0 + nxt*2304);
            #pragma unroll
            for (int t = 0; t < 2; t++) {
                uint32_t ah0 = pack2h(areg[t].x, areg[t].y);
                uint32_t ah1 = pack2h(areg[t].z, areg[t].w);
                int awi = am[t]*AWS + (ak[t] >> 1);
                *(uint2*)&AhN[awi] = make_uint2(ah0, ah1);
                uint32_t bh0 = pack2h(breg[t].x, breg[t].y);
                uint32_t bh1 = pack2h(breg[t].z, breg[t].w);
                uint32_t bl0 = split_lo2h(bh0, breg[t].x, breg[t].y);
                uint32_t bl1 = split_lo2h(bh1, breg[t].z, breg[t].w);
                int bwi = (bk[t]*BSTRB + bn[t]) >> 1;
                *(uint2*)&BhN[bwi] = make_uint2(bh0, bh1);
                *(uint2*)&BlN[bwi] = make_uint2(bl0, bl1);
            }
        }
        __syncthreads();
    }
    finish(c, (float*)smraw);
}

// K1: qkv = w_qkv[384,512] @ x[b,512,2304]; DIRECT scatter (R13-proven).
__global__ void __launch_bounds__(256) qkv_mma(const float* __restrict__ x,
                                               const float* __restrict__ w) {
    const int b = blockIdx.z;
    const float* xb = x + (size_t)b * CC * NN;
    gemm_body<K_QKV>(w, xb, [b](const float (&c)[2][2][4], float*) {
        const int lane = threadIdx.x & 31;
        const int wid  = threadIdx.x >> 5;
        const int gr   = lane >> 2;
        const int ct   = lane & 3;
        const int wm   = (wid & 1) * 32;
        const int wn   = (wid >> 1) * 16;
        const int mBase = blockIdx.y * 64;
        const int nBase = blockIdx.x * 64;
        #pragma unroll
        for (int mt = 0; mt < 2; mt++)
        #pragma unroll
        for (int nt = 0; nt < 2; nt++)
        #pragma unroll
        for (int e = 0; e < 4; e++) {
            int m = mBase + wm + mt*16 + gr + ((e >= 2) ? 8 : 0);
            int n = nBase + wn + nt*8 + 2*ct + (e & 1);
            int part = m >> 7;
            int t2 = m & 127, h = t2 >> 4, d = t2 & 15;
            int idx = ((b*HEADS + h)*NN + n)*DPH + d;
            float val = c[mt][nt][e];
            if      (part == 0) g_q[idx] = val;
            else if (part == 1) g_k[idx] = val;
            else                g_v[idx] = val;
        }
    });
}

// K4: out = w_out @ ao. Paired stores + fused deterministic BN partials.
__global__ void __launch_bounds__(256) proj_mma(const float* __restrict__ w,
                                                float* __restrict__ out) {
    const int b = blockIdx.z;
    const float* ao = g_ao + (size_t)b * TOT * NN;
    gemm_body<K_PRJ>(w, ao, [b, out](const float (&c)[2][2][4], float* scratch) {
        const int tid  = threadIdx.x;
        const int lane = tid & 31;
        const int wid  = tid >> 5;
        const int gr   = lane >> 2;
        const int ct   = lane & 3;
        const int wm   = (wid & 1) * 32;
        const int wn   = (wid >> 1) * 16;
        const int mBase = blockIdx.y * 64;
        const int nBase = blockIdx.x * 64;
        #pragma unroll
        for (int mt = 0; mt < 2; mt++)
        #pragma unroll
        for (int nt = 0; nt < 2; nt++) {
            int m0 = mBase + wm + mt*16 + gr;
            int n0 = nBase + wn + nt*8 + 2*ct;
            *(float2*)&out[((size_t)b*CC + m0    )*NN + n0] = make_float2(c[mt][nt][0], c[mt][nt][1]);
            *(float2*)&out[((size_t)b*CC + m0 + 8)*NN + n0] = make_float2(c[mt][nt][2], c[mt][nt][3]);
        }
        #pragma unroll
        for (int mt = 0; mt < 2; mt++)
        #pragma unroll
        for (int half = 0; half < 2; half++) {
            float s = 0.f, s2 = 0.f;
            #pragma unroll
            for (int nt = 0; nt < 2; nt++) {
                float v0 = c[mt][nt][half*2 + 0];
                float v1 = c[mt][nt][half*2 + 1];
                s  += v0 + v1;
                s2 += v0*v0 + v1*v1;
            }
            s  += __shfl_xor_sync(0xffffffffu, s, 1);
            s  += __shfl_xor_sync(0xffffffffu, s, 2);
            s2 += __shfl_xor_sync(0xffffffffu, s2, 1);
            s2 += __shfl_xor_sync(0xffffffffu, s2, 2);
            if (ct == 0) {
                int rloc = wm + mt*16 + gr + half*8;
                scratch[(rloc*4 + (wid >> 1))*2 + 0] = s;
                scratch[(rloc*4 + (wid >> 1))*2 + 1] = s2;
            }
        }
        __syncthreads();
        if (tid < 128) {
            int rloc = tid >> 1, q = tid & 1;
            float v = scratch[(rloc*4+0)*2 + q] + scratch[(rloc*4+1)*2 + q]
                    + scratch[(rloc*4+2)*2 + q] + scratch[(rloc*4+3)*2 + q];
            int slot = blockIdx.x*2 + b;
            g_bnpart2[((size_t)slot*CC + (mBase + rloc))*2 + q] = v;
        }
    });
}

// ===========================================================================
// K3: attention (unchanged, proven): 3-way key split, tf32 S, f16 PV.
// ===========================================================================
#define KSTR 20
#define VWS  68
__global__ void __launch_bounds__(256) attn_mma(const float* __restrict__ temperature) {
    __shared__ float Ks[128*KSTR];
    __shared__ __align__(4) uint32_t Vw[16*VWS];
    const int b     = blockIdx.z;
    const int h     = blockIdx.y;
    const int split = blockIdx.x / QBLKS;
    const int qblk  = blockIdx.x % QBLKS;
    const int tid  = threadIdx.x;
    const int wid  = tid >> 5;
    const int lane = tid & 31;
    const int gr   = lane >> 2;
    const int ct   = lane & 3;
    const float scale = __ldg(&temperature[h]) * 1.4426950408889634f;
    const int base = (b*HEADS + h) * NN * DPH;
    const int qw   = qblk * 128 + wid * 16;
    const int cstart = split * CHUNK;

    uint32_t qa[2][4];
    {
        const float* q0 = g_q + base + (qw+gr  )*DPH;
        const float* q1 = g_q + base + (qw+gr+8)*DPH;
        float r0[4], r1[4];
        #pragma unroll
        for (int j = 0; j < 4; j++) { r0[j] = q0[ct + 4*j]; r1[j] = q1[ct + 4*j]; }
        float s0 = r0[0]*r0[0] + r0[1]*r0[1] + r0[2]*r0[2] + r0[3]*r0[3];
        float s1 = r1[0]*r1[0] + r1[1]*r1[1] + r1[2]*r1[2] + r1[3]*r1[3];
        s0 += __shfl_xor_sync(0xffffffffu, s0, 1);
        s0 += __shfl_xor_sync(0xffffffffu, s0, 2);
        s1 += __shfl_xor_sync(0xffffffffu, s1, 1);
        s1 += __shfl_xor_sync(0xffffffffu, s1, 2);
        float i0 = scale / fmaxf(sqrtf(s0), 1e-12f);
        float i1 = scale / fmaxf(sqrtf(s1), 1e-12f);
        qa[0][0] = f2tf32(r0[0]*i0); qa[0][1] = f2tf32(r1[0]*i1);
        qa[0][2] = f2tf32(r0[1]*i0); qa[0][3] = f2tf32(r1[1]*i1);
        qa[1][0] = f2tf32(r0[2]*i0); qa[1][1] = f2tf32(r1[2]*i1);
        qa[1][2] = f2tf32(r0[3]*i0); qa[1][3] = f2tf32(r1[3]*i1);
    }

    float out0[4] = {};
    float out1[4] = {};
    float l0 = 0.f, l1 = 0.f;
    const uint32_t* ksu = (const uint32_t*)Ks;
    const int koff = gr * KSTR + ct;

    for (int t0 = 0; t0 < CHUNK; t0 += 128) {
        __syncthreads();
        {
            const float4* kg = (const float4*)(g_k + base + (cstart + t0)*16);
            const float4* vg = (const float4*)(g_v + base + (cstart + t0)*16);
            __half* vb = (__half*)Vw;
            #pragma unroll
            for (int t = 0; t < 2; t++) {
                int i4 = tid + t * 256;
                int r = i4 >> 2, cc4 = (i4 & 3) * 4;
                float4 kv = kg[i4];
                float s = kv.x*kv.x + kv.y*kv.y + kv.z*kv.z + kv.w*kv.w;
                s += __shfl_xor_sync(0xffffffffu, s, 1);
                s += __shfl_xor_sync(0xffffffffu, s, 2);
                float inv = 1.0f / fmaxf(sqrtf(s), 1e-12f);
                kv.x = tf32_round(kv.x * inv); kv.y = tf32_round(kv.y * inv);
                kv.z = tf32_round(kv.z * inv); kv.w = tf32_round(kv.w * inv);
                *(float4*)&Ks[r*KSTR + cc4] = kv;
                float4 vv = vg[i4];
                int half_i = r & 1, k2 = r >> 1;
                vb[((cc4+0)*VWS + k2)*2 + half_i] = __float2half_rn(vv.x);
                vb[((cc4+1)*VWS + k2)*2 + half_i] = __float2half_rn(vv.y);
                vb[((cc4+2)*VWS + k2)*2 + half_i] = __float2half_rn(vv.z);
                vb[((cc4+3)*VWS + k2)*2 + half_i] = __float2half_rn(vv.w);
            }
        }
        __syncthreads();
        #pragma unroll 4
        for (int kb16 = 0; kb16 < 8; kb16++) {
            float sa[4] = {};
            {
                int ka = (kb16*16)*KSTR + koff;
                mma_tf32(sa, qa[0], ksu[ka],   ksu[ka+4]);
                mma_tf32(sa, qa[1], ksu[ka+8], ksu[ka+12]);
            }
            float sb[4] = {};
            {
                int ka = (kb16*16 + 8)*KSTR + koff;
                mma_tf32(sb, qa[0], ksu[ka],   ksu[ka+4]);
                mma_tf32(sb, qa[1], ksu[ka+8], ksu[ka+12]);
            }
            float pa0 = ex2f(sa[0]), pa1 = ex2f(sa[1]);
            float pa2 = ex2f(sa[2]), pa3 = ex2f(sa[3]);
            float pb0 = ex2f(sb[0]), pb1 = ex2f(sb[1]);
            float pb2 = ex2f(sb[2]), pb3 = ex2f(sb[3]);
            l0 += (pa0 + pa1) + (pb0 + pb1);
            l1 += (pa2 + pa3) + (pb2 + pb3);
            uint32_t pH[4];
            pH[0] = pack2h(pa0, pa1);
            pH[1] = pack2h(pa2, pa3);
            pH[2] = pack2h(pb0, pb1);
            pH[3] = pack2h(pb2, pb3);
            {
                int kbase = kb16*8 + ct;
                mma_f16(out0, pH, Vw[gr*VWS + kbase],     Vw[gr*VWS + kbase + 4]);
                mma_f16(out1, pH, Vw[(8+gr)*VWS + kbase], Vw[(8+gr)*VWS + kbase + 4]);
            }
        }
    }
    l0 += __shfl_xor_sync(0xffffffffu, l0, 1);
    l0 += __shfl_xor_sync(0xffffffffu, l0, 2);
    l1 += __shfl_xor_sync(0xffffffffu, l1, 1);
    l1 += __shfl_xor_sync(0xffffffffu, l1, 2);

    const int bh = b*HEADS + h;
    float* pp = g_part + ((size_t)(split*BB*HEADS + bh) * DPH) * NN;
    {
        int d0 = 2*ct;
        pp[(size_t)(d0    )*NN + qw + gr    ] = out0[0];
        pp[(size_t)(d0 + 1)*NN + qw + gr    ] = out0[1];
        pp[(size_t)(d0    )*NN + qw + gr + 8] = out0[2];
        pp[(size_t)(d0 + 1)*NN + qw + gr + 8] = out0[3];
        pp[(size_t)(8 + d0    )*NN + qw + gr    ] = out1[0];
        pp[(size_t)(8 + d0 + 1)*NN + qw + gr    ] = out1[1];
        pp[(size_t)(8 + d0    )*NN + qw + gr + 8] = out1[2];
        pp[(size_t)(8 + d0 + 1)*NN + qw + gr + 8] = out1[3];
        float* lp = g_lsum + (size_t)(split*BB*HEADS + bh) * NN;
        lp[qw + gr    ] = l0;
        lp[qw + gr + 8] = l1;
    }
}

// K3b: combine split partials, normalize, write g_ao. Coalesced.
__global__ void __launch_bounds__(256) combine_kernel() {
    int idx = blockIdx.x * 256 + threadIdx.x;
    const int NQ4 = NN / 4;
    int n4 = idx % NQ4;
    int r  = idx / NQ4;
    int d  = r & 15;
    int bh = r >> 4;
    float4 acc = make_float4(0.f, 0.f, 0.f, 0.f);
    float4 lac = make_float4(0.f, 0.f, 0.f, 0.f);
    #pragma unroll
    for (int s = 0; s < NSPLIT; s++) {
        float4 p = *(const float4*)&g_part[((size_t)(s*BB*HEADS + bh) * DPH + d) * NN + n4*4];
        float4 l = *(const float4*)&g_lsum[(size_t)(s*BB*HEADS + bh) * NN + n4*4];
        acc.x += p.x; acc.y += p.y; acc.z += p.z; acc.w += p.w;
        lac.x += l.x; lac.y += l.y; lac.z += l.z; lac.w += l.w;
    }
    float4 o;
    o.x = acc.x / lac.x; o.y = acc.y / lac.y;
    o.z = acc.z / lac.z; o.w = acc.w / lac.w;
    *(float4*)&g_ao[(size_t)(bh*DPH + d) * NN + n4*4] = o;
}

// K5b: finalize scale/shift per channel from NSLOT proj-block partials.
__global__ void __launch_bounds__(256) bn_finalize(const float* __restrict__ gamma,
                                                   const float* __restrict__ beta) {
    int c = blockIdx.x * 256 + threadIdx.x;
    if (c >= CC) return;
    float s = 0.f, s2 = 0.f;
    #pragma unroll 8
    for (int sl = 0; sl < NSLOT; sl++) {
        s  += g_bnpart2[((size_t)sl*CC + c)*2 + 0];
        s2 += g_bnpart2[((size_t)sl*CC + c)*2 + 1];
    }
    const float invN = 1.0f / (BB * NN);
    float mean = s * invN;
    float var  = fmaxf(s2 * invN - mean * mean, 0.f);
    float sc   = rsqrtf(var + 1e-5f) * gamma[c];
    g_bnscale[c] = sc;
    g_bnshift[c] = beta[c] - mean * sc;
}

// K5c: apply. grid = BB*CC*NN/4/256 = 2304 blocks.
__global__ void __launch_bounds__(256) bn_apply(float* __restrict__ out) {
    int fi = blockIdx.x * 256 + threadIdx.x;
    int c  = ((fi * 4) / NN) % CC;
    float sc = g_bnscale[c], sh = g_bnshift[c];
    float4* p = (float4*)out + fi;
    float4 v = *p;
    v.x = fmaf(v.x, sc, sh); v.y = fmaf(v.y, sc, sh);
    v.z = fmaf(v.z, sc, sh); v.w = fmaf(v.w, sc, sh);
    *p = v;
}

// ---------------------------------------------------------------------------
extern "C" void kernel_launch(void* const* d_in, const int* in_sizes, int n_in,
                              void* d_out, int out_size) {
    const float* x      = (const float*)d_in[0];
    const float* w_qkv  = (const float*)d_in[1];
    const float* temper = (const float*)d_in[2];
    const float* w_out  = (const float*)d_in[3];
    const float* gamma  = (const float*)d_in[4];
    const float* beta   = (const float*)d_in[5];
    float* out = (float*)d_out;

    qkv_mma <<<dim3(NN/64, M_QKV/64, BB), 256>>>(x, w_qkv);
    attn_mma<<<dim3(QBLKS*NSPLIT, HEADS, BB), 256>>>(temper);
    combine_kernel<<<(BB*HEADS*DPH*NN/4)/256, 256>>>();
    proj_mma<<<dim3(NN/64, M_PRJ/64, BB), 256>>>(w_out, out);
    bn_finalize<<<2, 256>>>(gamma, beta);
    bn_apply<<<(BB*CC*NN/4)/256, 256>>>(out);
}